// round 4
// baseline (speedup 1.0000x reference)
#include <cuda_runtime.h>
#include <cstdint>

typedef unsigned long long u64;

#define IMG_W 512
#define IMG_H 512

// ---- f32x2 packed helpers ----
__device__ __forceinline__ u64 pack2(float lo, float hi) {
    u64 r;
    asm("mov.b64 %0, {%1, %2};"
        : "=l"(r) : "r"(__float_as_uint(lo)), "r"(__float_as_uint(hi)));
    return r;
}

__device__ __forceinline__ void fma2(u64& d, u64 a, u64 b) {
    asm("fma.rn.f32x2 %0, %1, %2, %0;" : "+l"(d) : "l"(a), "l"(b));
}

// (hi(a), lo(b)) -> the odd-aligned sliding pair; ptxas collapses to 2 MOVs.
__device__ __forceinline__ u64 pack_hl(u64 a, u64 b) {
    u64 d;
    asm("{\n\t"
        ".reg .b32 al, ah, bl, bh;\n\t"
        "mov.b64 {al, ah}, %1;\n\t"
        "mov.b64 {bl, bh}, %2;\n\t"
        "mov.b64 %0, {ah, bl};\n\t"
        "}" : "=l"(d) : "l"(a), "l"(b));
    return d;
}

// Thread: 4 output rows x 4 output cols, all math on f32x2 pairs.
// Block: 256 threads = 128 col-threads (512 cols) x 2 row groups (8 rows).
// Grid: (64 row tiles, 128 images).
__global__ __launch_bounds__(256)
void conv5x5_f32x2_kernel(const float* __restrict__ X,
                          const float* __restrict__ K,
                          float* __restrict__ O) {
    const int tx   = threadIdx.x & 127;
    const int tg   = threadIdx.x >> 7;
    const int col  = tx << 2;                        // multiple of 4 -> 16B aligned
    const int img  = blockIdx.y;
    const int row0 = (blockIdx.x << 3) + (tg << 2);

    // Weights: 7 vector loads, then broadcast-pack (w,w) x25.
    float kw[25];
    const float4* K4 = reinterpret_cast<const float4*>(K);
    #pragma unroll
    for (int i = 0; i < 6; i++) {
        float4 v = __ldg(K4 + i);
        kw[4*i+0] = v.x; kw[4*i+1] = v.y; kw[4*i+2] = v.z; kw[4*i+3] = v.w;
    }
    kw[24] = __ldg(K + 24);
    u64 wp[25];
    #pragma unroll
    for (int i = 0; i < 25; i++) wp[i] = pack2(kw[i], kw[i]);

    const float* in = X + (size_t)img * (IMG_W * IMG_H);

    u64 acc[4][2];
    #pragma unroll
    for (int ro = 0; ro < 4; ro++) { acc[ro][0] = 0ull; acc[ro][1] = 0ull; }

    #pragma unroll
    for (int lr = 0; lr < 8; lr++) {
        const int r = row0 - 2 + lr;                  // input row (warp-uniform test)
        u64 p0, p2, p4, p6;                           // even-aligned pairs, direct from loads
        if (r >= 0 && r < IMG_H) {
            const float* rp = in + (size_t)r * IMG_W;
            p0 = (col >= 2)
                ? *reinterpret_cast<const u64*>(rp + col - 2) : 0ull;        // (x[c-2],x[c-1])
            ulonglong2 m = *reinterpret_cast<const ulonglong2*>(rp + col);   // LDG.128
            p2 = m.x;                                                        // (x[c],  x[c+1])
            p4 = m.y;                                                        // (x[c+2],x[c+3])
            p6 = (col + 4 < IMG_W)
                ? *reinterpret_cast<const u64*>(rp + col + 4) : 0ull;        // (x[c+4],x[c+5])
        } else {
            p0 = p2 = p4 = p6 = 0ull;
        }
        // Odd-aligned pairs: only 3 packs per row.
        u64 p1 = pack_hl(p0, p2);
        u64 p3 = pack_hl(p2, p4);
        u64 p5 = pack_hl(p4, p6);
        u64 p[7] = {p0, p1, p2, p3, p4, p5, p6};

        // Input row r feeds output rows ro with kr = lr - ro in [0,4]
        #pragma unroll
        for (int ro = 0; ro < 4; ro++) {
            const int kr = lr - ro;
            if (kr < 0 || kr > 4) continue;
            #pragma unroll
            for (int kc = 0; kc < 5; kc++) {
                fma2(acc[ro][0], p[kc],     wp[kr*5 + kc]);  // outputs (col, col+1)
                fma2(acc[ro][1], p[kc + 2], wp[kr*5 + kc]);  // outputs (col+2, col+3)
            }
        }
    }

    float* op = O + (size_t)img * (IMG_W * IMG_H) + (size_t)row0 * IMG_W + col;
    #pragma unroll
    for (int ro = 0; ro < 4; ro++) {
        ulonglong2 v;
        v.x = acc[ro][0];
        v.y = acc[ro][1];
        *reinterpret_cast<ulonglong2*>(op + (size_t)ro * IMG_W) = v;  // STG.128
    }
}

extern "C" void kernel_launch(void* const* d_in, const int* in_sizes, int n_in,
                              void* d_out, int out_size) {
    const float* X = (const float*)d_in[0];   // (4,32,512,512) f32
    const float* K = (const float*)d_in[1];   // (5,5) f32
    float* O = (float*)d_out;                 // (4,32,512,512) f32
    (void)in_sizes; (void)n_in; (void)out_size;  // stride=1, padding=2 fixed

    dim3 grid(IMG_H / 8, 4 * 32);             // 64 row tiles x 128 images
    conv5x5_f32x2_kernel<<<grid, 256>>>(X, K, O);
}